// round 1
// baseline (speedup 1.0000x reference)
#include <cuda_runtime.h>
#include <math.h>

// ---------------- problem constants (fixed dataset shapes) ----------------
#define N_MAX   20000
#define E0_MAX  320000
#define ET_MAX  (E0_MAX + N_MAX)
#define FIN     128
#define H1      8
#define C1      64
#define D1      512
#define D2      128
#define NGRAPH  256
#define NOUT    2

// ---------------- device scratch (static: no allocations allowed) ----------
__device__ float g_h1   [N_MAX * D1];   // x @ W1^T
__device__ float g_hout1[N_MAX * D1];   // relu(conv1 out)
__device__ float g_h2   [N_MAX * D2];   // hout1 @ W2^T
__device__ float g_hout2[N_MAX * D2];   // relu(conv2 out)
__device__ float g_asrc1[N_MAX * H1];
__device__ float g_adst1[N_MAX * H1];
__device__ float g_asrc2[N_MAX];
__device__ float g_adst2[N_MAX];
__device__ float g_e1   [ET_MAX * H1];  // fallback per-edge buffer (deg > CAP)
__device__ float g_e2   [ET_MAX];
__device__ int   g_counts [N_MAX + 1];
__device__ int   g_offsets[N_MAX + 1];
__device__ int   g_cursor [N_MAX + 1];
__device__ int   g_bsums  [64];
__device__ int   g_ssrc   [ET_MAX];     // CSR-by-dst: src node per sorted edge
__device__ float g_pooled [NGRAPH * D2];

// ---------------- utility kernels ----------------
__global__ void k_zero(int Nn) {
    int i = blockIdx.x * blockDim.x + threadIdx.x;
    if (i <= Nn) g_counts[i] = 0;
    if (i < NGRAPH * D2) g_pooled[i] = 0.f;
}

__global__ void k_count(const int* __restrict__ ei, int E0, int ET) {
    int t = blockIdx.x * blockDim.x + threadIdx.x;
    if (t >= ET) return;
    int d = (t < E0) ? ei[E0 + t] : (t - E0);
    atomicAdd(&g_counts[d], 1);
}

__global__ void k_scan1(int Nn) {
    __shared__ int sh[1024];
    int t = threadIdx.x, i = blockIdx.x * 1024 + t;
    int v = (i < Nn) ? g_counts[i] : 0;
    sh[t] = v;
    __syncthreads();
    for (int s = 1; s < 1024; s <<= 1) {
        int add = (t >= s) ? sh[t - s] : 0;
        __syncthreads();
        sh[t] += add;
        __syncthreads();
    }
    if (i < Nn) g_offsets[i + 1] = sh[t];
    if (t == 1023) g_bsums[blockIdx.x] = sh[1023];
}

__global__ void k_scan2(int nb) {
    if (threadIdx.x == 0) {
        int run = 0;
        for (int b = 0; b < nb; b++) { int v = g_bsums[b]; g_bsums[b] = run; run += v; }
    }
}

__global__ void k_scan3(int Nn) {
    int t = threadIdx.x, i = blockIdx.x * 1024 + t;
    if (i < Nn) {
        int v = g_offsets[i + 1] + g_bsums[blockIdx.x];
        g_offsets[i + 1] = v;
        g_cursor[i + 1]  = v;
    }
    if (i == 0) { g_offsets[0] = 0; g_cursor[0] = 0; }
}

__global__ void k_scatter(const int* __restrict__ ei, int E0, int ET) {
    int t = blockIdx.x * blockDim.x + threadIdx.x;
    if (t >= ET) return;
    int s, d;
    if (t < E0) { s = ei[t]; d = ei[E0 + t]; }
    else        { s = d = t - E0; }
    int pos = atomicAdd(&g_cursor[d], 1);
    g_ssrc[pos] = s;
}

// ---------------- SGEMM: C[M,N] = A[M,K] * B[N,K]^T  (both row-major, K-major) ----
#define TM 64
#define TN 64
#define TK 16
__global__ void __launch_bounds__(256)
k_sgemm_nt(const float* __restrict__ A, const float* __restrict__ B,
           float* __restrict__ C, int M, int N, int K) {
    __shared__ float As[TK][TM + 4];
    __shared__ float Bs[TK][TN + 4];
    int tid = threadIdx.x;
    int bm = blockIdx.x * TM, bn = blockIdx.y * TN;
    int tx = tid & 15, ty = tid >> 4;
    int lk = tid & 15, lr = tid >> 4;     // load indices
    float acc[4][4];
#pragma unroll
    for (int i = 0; i < 4; i++)
#pragma unroll
        for (int j = 0; j < 4; j++) acc[i][j] = 0.f;

    for (int k0 = 0; k0 < K; k0 += TK) {
#pragma unroll
        for (int p = 0; p < 4; p++) {
            int m = bm + lr + 16 * p;
            As[lk][lr + 16 * p] = (m < M) ? A[(size_t)m * K + k0 + lk] : 0.f;
            int n = bn + lr + 16 * p;
            Bs[lk][lr + 16 * p] = (n < N) ? B[(size_t)n * K + k0 + lk] : 0.f;
        }
        __syncthreads();
#pragma unroll
        for (int kk = 0; kk < TK; kk++) {
            float4 a4 = *(const float4*)&As[kk][ty * 4];
            float4 b4 = *(const float4*)&Bs[kk][tx * 4];
            float a[4] = {a4.x, a4.y, a4.z, a4.w};
            float b[4] = {b4.x, b4.y, b4.z, b4.w};
#pragma unroll
            for (int i = 0; i < 4; i++)
#pragma unroll
                for (int j = 0; j < 4; j++) acc[i][j] = fmaf(a[i], b[j], acc[i][j]);
        }
        __syncthreads();
    }
#pragma unroll
    for (int i = 0; i < 4; i++) {
        int m = bm + ty * 4 + i;
        if (m < M) {
            float4 r = make_float4(acc[i][0], acc[i][1], acc[i][2], acc[i][3]);
            *(float4*)&C[(size_t)m * N + bn + tx * 4] = r;
        }
    }
}

// ---------------- attention coefficients ----------------
// conv1: one block (64 thr) per node; per-head dot of h row with att vectors
__global__ void __launch_bounds__(64)
k_attn1(const float* __restrict__ att_s, const float* __restrict__ att_d) {
    int n = blockIdx.x, c = threadIdx.x;
    const float* row = g_h1 + (size_t)n * D1;
    float ps[H1], pd[H1];
#pragma unroll
    for (int h = 0; h < H1; h++) {
        float v = row[h * C1 + c];
        ps[h] = v * att_s[h * C1 + c];
        pd[h] = v * att_d[h * C1 + c];
    }
#pragma unroll
    for (int h = 0; h < H1; h++) {
#pragma unroll
        for (int o = 16; o; o >>= 1) {
            ps[h] += __shfl_xor_sync(0xffffffffu, ps[h], o);
            pd[h] += __shfl_xor_sync(0xffffffffu, pd[h], o);
        }
    }
    __shared__ float ss[2][H1], sd[2][H1];
    int w = c >> 5, l = c & 31;
    if (l == 0) {
#pragma unroll
        for (int h = 0; h < H1; h++) { ss[w][h] = ps[h]; sd[w][h] = pd[h]; }
    }
    __syncthreads();
    if (c < H1) {
        g_asrc1[n * H1 + c] = ss[0][c] + ss[1][c];
        g_adst1[n * H1 + c] = sd[0][c] + sd[1][c];
    }
}

// conv2: warp per node
__global__ void k_attn2(const float* __restrict__ att_s, const float* __restrict__ att_d, int Nn) {
    int t = blockIdx.x * blockDim.x + threadIdx.x;
    int n = t >> 5, lane = t & 31;
    if (n >= Nn) return;
    float4 v = *(const float4*)(g_h2 + (size_t)n * D2 + lane * 4);
    float4 a = *(const float4*)(att_s + lane * 4);
    float4 b = *(const float4*)(att_d + lane * 4);
    float sa = v.x * a.x + v.y * a.y + v.z * a.z + v.w * a.w;
    float sb = v.x * b.x + v.y * b.y + v.z * b.z + v.w * b.w;
#pragma unroll
    for (int o = 16; o; o >>= 1) {
        sa += __shfl_xor_sync(0xffffffffu, sa, o);
        sb += __shfl_xor_sync(0xffffffffu, sb, o);
    }
    if (lane == 0) { g_asrc2[n] = sa; g_adst2[n] = sb; }
}

// ---------------- conv1 aggregation: one block (128 thr) per destination node ----
#define AGG_CAP 1024
__global__ void __launch_bounds__(128)
k_agg1(const float* __restrict__ bias) {
    __shared__ float s_e[AGG_CAP * H1];   // 32 KB
    int n = blockIdx.x, tid = threadIdx.x;
    int off = g_offsets[n];
    int deg = g_offsets[n + 1] - off;
    const int* src = g_ssrc + off;
    float* ebuf = (deg <= AGG_CAP) ? s_e : (g_e1 + (size_t)off * H1);

    float ad[H1];
#pragma unroll
    for (int h = 0; h < H1; h++) ad[h] = g_adst1[n * H1 + h];

    for (int i = tid; i < deg; i += 128) {
        int s = src[i];
        const float* as = g_asrc1 + (size_t)s * H1;
#pragma unroll
        for (int h = 0; h < H1; h++) {
            float v = as[h] + ad[h];
            ebuf[i * H1 + h] = (v > 0.f) ? v : 0.2f * v;
        }
    }
    __syncthreads();

    if (tid < H1) {
        float m = -1e30f;
        for (int i = 0; i < deg; i++) m = fmaxf(m, ebuf[i * H1 + tid]);
        float sum = 0.f;
        for (int i = 0; i < deg; i++) {
            float ex = __expf(ebuf[i * H1 + tid] - m);
            ebuf[i * H1 + tid] = ex;
            sum += ex;
        }
        float inv = 1.f / (sum + 1e-16f);
        for (int i = 0; i < deg; i++) ebuf[i * H1 + tid] *= inv;
    }
    __syncthreads();

    int base = tid * 4;
    int hh = base >> 6;                 // channel block -> head (C1 = 64)
    float a0 = 0.f, a1 = 0.f, a2 = 0.f, a3 = 0.f;
    for (int i = 0; i < deg; i++) {
        float al = ebuf[i * H1 + hh];
        const float4 v = *(const float4*)(g_h1 + (size_t)src[i] * D1 + base);
        a0 = fmaf(al, v.x, a0);
        a1 = fmaf(al, v.y, a1);
        a2 = fmaf(al, v.z, a2);
        a3 = fmaf(al, v.w, a3);
    }
    float4 r;
    r.x = fmaxf(a0 + bias[base + 0], 0.f);
    r.y = fmaxf(a1 + bias[base + 1], 0.f);
    r.z = fmaxf(a2 + bias[base + 2], 0.f);
    r.w = fmaxf(a3 + bias[base + 3], 0.f);
    *(float4*)(g_hout1 + (size_t)n * D1 + base) = r;
}

// ---------------- conv2 aggregation: one warp per destination node ----------
__global__ void __launch_bounds__(128)
k_agg2(const float* __restrict__ bias, int Nn) {
    __shared__ float s_e[4][AGG_CAP];     // 16 KB
    int wid = threadIdx.x >> 5, lane = threadIdx.x & 31;
    int n = blockIdx.x * 4 + wid;
    if (n >= Nn) return;
    int off = g_offsets[n];
    int deg = g_offsets[n + 1] - off;
    const int* src = g_ssrc + off;
    float* ebuf = (deg <= AGG_CAP) ? s_e[wid] : (g_e2 + off);

    float ad = g_adst2[n];
    for (int i = lane; i < deg; i += 32) {
        float v = g_asrc2[src[i]] + ad;
        ebuf[i] = (v > 0.f) ? v : 0.2f * v;
    }
    __syncwarp();
    float m = -1e30f;
    for (int i = lane; i < deg; i += 32) m = fmaxf(m, ebuf[i]);
#pragma unroll
    for (int o = 16; o; o >>= 1) m = fmaxf(m, __shfl_xor_sync(0xffffffffu, m, o));
    float sum = 0.f;
    for (int i = lane; i < deg; i += 32) {
        float ex = __expf(ebuf[i] - m);
        ebuf[i] = ex;
        sum += ex;
    }
#pragma unroll
    for (int o = 16; o; o >>= 1) sum += __shfl_xor_sync(0xffffffffu, sum, o);
    float inv = 1.f / (sum + 1e-16f);
    for (int i = lane; i < deg; i += 32) ebuf[i] *= inv;
    __syncwarp();

    int base = lane * 4;
    float a0 = 0.f, a1 = 0.f, a2 = 0.f, a3 = 0.f;
    for (int i = 0; i < deg; i++) {
        float al = ebuf[i];
        const float4 v = *(const float4*)(g_h2 + (size_t)src[i] * D2 + base);
        a0 = fmaf(al, v.x, a0);
        a1 = fmaf(al, v.y, a1);
        a2 = fmaf(al, v.z, a2);
        a3 = fmaf(al, v.w, a3);
    }
    float4 r;
    r.x = fmaxf(a0 + bias[base + 0], 0.f);
    r.y = fmaxf(a1 + bias[base + 1], 0.f);
    r.z = fmaxf(a2 + bias[base + 2], 0.f);
    r.w = fmaxf(a3 + bias[base + 3], 0.f);
    *(float4*)(g_hout2 + (size_t)n * D2 + base) = r;
}

// ---------------- attention pooling: one warp per node, atomic segment-sum ----
__global__ void k_pool(const int* __restrict__ batch,
                       const float* __restrict__ wat, const float* __restrict__ bat,
                       const float* __restrict__ wma, const float* __restrict__ bma,
                       int Nn) {
    int t = blockIdx.x * blockDim.x + threadIdx.x;
    int n = t >> 5, lane = t & 31;
    if (n >= Nn) return;
    float4 v = *(const float4*)(g_hout2 + (size_t)n * D2 + lane * 4);
    float4 a = *(const float4*)(wat + lane * 4);
    float4 m = *(const float4*)(wma + lane * 4);
    float sa = v.x * a.x + v.y * a.y + v.z * a.z + v.w * a.w;
    float sm = v.x * m.x + v.y * m.y + v.z * m.z + v.w * m.w;
#pragma unroll
    for (int o = 16; o; o >>= 1) {
        sa += __shfl_xor_sync(0xffffffffu, sa, o);
        sm += __shfl_xor_sync(0xffffffffu, sm, o);
    }
    sa += bat[0];
    sm += bma[0];
    float w = sa * (1.f / (1.f + __expf(-sm)));
    int g = batch[n];
    float* p = &g_pooled[g * D2 + lane * 4];
    atomicAdd(p + 0, w * v.x);
    atomicAdd(p + 1, w * v.y);
    atomicAdd(p + 2, w * v.z);
    atomicAdd(p + 3, w * v.w);
}

// ---------------- final projection: [256,128] @ [128,2]^T + b -------------
__global__ void __launch_bounds__(64)
k_out(const float* __restrict__ Wo, const float* __restrict__ bo, float* __restrict__ out) {
    int g = blockIdx.x;
    int o = threadIdx.x >> 5, lane = threadIdx.x & 31;
    float s = 0.f;
#pragma unroll
    for (int i = 0; i < 4; i++) {
        int c = lane + 32 * i;
        s += g_pooled[g * D2 + c] * Wo[o * D2 + c];
    }
#pragma unroll
    for (int off = 16; off; off >>= 1) s += __shfl_xor_sync(0xffffffffu, s, off);
    if (lane == 0) out[g * NOUT + o] = s + bo[o];
}

// ---------------- launcher ----------------
extern "C" void kernel_launch(void* const* d_in, const int* in_sizes, int n_in,
                              void* d_out, int out_size) {
    const float* x    = (const float*)d_in[0];
    const int*   ei   = (const int*)  d_in[1];
    const int*   bat_ = (const int*)  d_in[2];
    const float* W1   = (const float*)d_in[3];
    const float* as1  = (const float*)d_in[4];
    const float* ad1  = (const float*)d_in[5];
    const float* b1   = (const float*)d_in[6];
    const float* W2   = (const float*)d_in[7];
    const float* as2  = (const float*)d_in[8];
    const float* ad2  = (const float*)d_in[9];
    const float* b2   = (const float*)d_in[10];
    const float* wat  = (const float*)d_in[11];
    const float* batn = (const float*)d_in[12];
    const float* wma  = (const float*)d_in[13];
    const float* bma  = (const float*)d_in[14];
    const float* Wo   = (const float*)d_in[15];
    const float* bo   = (const float*)d_in[16];
    float* out = (float*)d_out;

    int Nn = in_sizes[0] / FIN;
    int E0 = in_sizes[1] / 2;
    int ET = E0 + Nn;

    float *p_h1, *p_hout1, *p_h2;
    cudaGetSymbolAddress((void**)&p_h1, g_h1);
    cudaGetSymbolAddress((void**)&p_hout1, g_hout1);
    cudaGetSymbolAddress((void**)&p_h2, g_h2);

    int zn = (Nn + 1 > NGRAPH * D2) ? (Nn + 1) : (NGRAPH * D2);
    k_zero<<<(zn + 255) / 256, 256>>>(Nn);
    k_count<<<(ET + 255) / 256, 256>>>(ei, E0, ET);
    int nb = (Nn + 1023) / 1024;
    k_scan1<<<nb, 1024>>>(Nn);
    k_scan2<<<1, 32>>>(nb);
    k_scan3<<<nb, 1024>>>(Nn);
    k_scatter<<<(ET + 255) / 256, 256>>>(ei, E0, ET);

    dim3 g1((Nn + TM - 1) / TM, D1 / TN);
    k_sgemm_nt<<<g1, 256>>>(x, W1, p_h1, Nn, D1, FIN);
    k_attn1<<<Nn, 64>>>(as1, ad1);
    k_agg1<<<Nn, 128>>>(b1);

    dim3 g2((Nn + TM - 1) / TM, D2 / TN);
    k_sgemm_nt<<<g2, 256>>>(p_hout1, W2, p_h2, Nn, D2, D1);
    k_attn2<<<(Nn * 32 + 255) / 256, 256>>>(as2, ad2, Nn);
    k_agg2<<<(Nn + 3) / 4, 128>>>(b2, Nn);

    k_pool<<<(Nn * 32 + 255) / 256, 256>>>(bat_, wat, batn, wma, bma, Nn);
    k_out<<<NGRAPH, 64>>>(Wo, bo, out);
}